// round 1
// baseline (speedup 1.0000x reference)
#include <cuda_runtime.h>
#include <cuda_bf16.h>

// Problem constants: B=1, H=8, L=4096, D=64, block 64x64, 16 samples per block.
#define NHEADS 8

__device__ int g_keep_list[NHEADS][64][64];
__device__ int g_keep_count[NHEADS][64];

// ---------------------------------------------------------------------------
// Kernel 1: pooled downsampled attention -> per-(h,qb) kept key-block list.
// Grid (64 qblocks, 8 heads), 256 threads.
// Dynamic smem: SK[256][65] + S[16][1025]  (132160 B)
// ---------------------------------------------------------------------------
__global__ __launch_bounds__(256, 1) void pool_mask_kernel(
    const float* __restrict__ q, const float* __restrict__ k,
    const int* __restrict__ sidq, const int* __restrict__ sidk)
{
    const int qb = blockIdx.x, h = blockIdx.y;
    const int t = threadIdx.x;
    extern __shared__ float dynp[];
    float* SK = dynp;               // 256 x 65 (one 256-col chunk of sampled K)
    float* S  = dynp + 256 * 65;    // 16 x 1025 (full sampled-score matrix)
    __shared__ float SQ[16 * 65];
    __shared__ int sqi[16], ski[16];
    __shared__ float rowinv[16];
    __shared__ float pooled[64];
    __shared__ float ppart[256];
    __shared__ int keepflag[64];
    __shared__ float total_s;

    if (t < 16) { sqi[t] = sidq[h * 16 + t]; ski[t] = sidk[h * 16 + t]; }
    __syncthreads();

    // Load 16 sampled q rows of this q-block (16 rows x 16 float4 = 256 slots).
    {
        int r = t >> 4, c4 = (t & 15) << 2;
        int grow = (qb << 6) + sqi[r];
        float4 val = *reinterpret_cast<const float4*>(q + ((((h << 12) + grow) << 6) + c4));
        SQ[r * 65 + c4 + 0] = val.x; SQ[r * 65 + c4 + 1] = val.y;
        SQ[r * 65 + c4 + 2] = val.z; SQ[r * 65 + c4 + 3] = val.w;
    }

    const int rt = t >> 6;   // 0..3  -> 4 q rows each
    const int ct = t & 63;   // 0..63 -> cols {ct, ct+64, ct+128, ct+192}

    // Score matrix S[16][1024] in 4 chunks of 256 sampled-k columns.
    for (int ck = 0; ck < 4; ck++) {
        __syncthreads();
        for (int i = t; i < 4096; i += 256) {
            int r = i >> 4, c4 = (i & 15) << 2;
            int kb = (ck << 4) + (r >> 4);
            int grow = (kb << 6) + ski[r & 15];
            float4 val = *reinterpret_cast<const float4*>(k + ((((h << 12) + grow) << 6) + c4));
            SK[r * 65 + c4 + 0] = val.x; SK[r * 65 + c4 + 1] = val.y;
            SK[r * 65 + c4 + 2] = val.z; SK[r * 65 + c4 + 3] = val.w;
        }
        __syncthreads();
        float sacc[4][4] = {};
        for (int d = 0; d < 64; d++) {
            float qv[4], kv[4];
            #pragma unroll
            for (int i = 0; i < 4; i++) qv[i] = SQ[((rt << 2) + i) * 65 + d];
            #pragma unroll
            for (int j = 0; j < 4; j++) kv[j] = SK[(ct + (j << 6)) * 65 + d];
            #pragma unroll
            for (int i = 0; i < 4; i++)
                #pragma unroll
                for (int j = 0; j < 4; j++) sacc[i][j] += qv[i] * kv[j];
        }
        #pragma unroll
        for (int i = 0; i < 4; i++)
            #pragma unroll
            for (int j = 0; j < 4; j++)
                S[((rt << 2) + i) * 1025 + (ck << 8) + ct + (j << 6)] = sacc[i][j] * 0.125f;
    }
    __syncthreads();

    // Row softmax (store unnormalized exp back, keep 1/rowsum).
    {
        int w = t >> 5, lane = t & 31;
        for (int rr = 0; rr < 2; rr++) {
            int r = (w << 1) + rr;
            float m = -1e30f;
            for (int c = lane; c < 1024; c += 32) m = fmaxf(m, S[r * 1025 + c]);
            #pragma unroll
            for (int off = 16; off; off >>= 1) m = fmaxf(m, __shfl_xor_sync(0xffffffffu, m, off));
            float sum = 0.f;
            for (int c = lane; c < 1024; c += 32) {
                float p = __expf(S[r * 1025 + c] - m);
                S[r * 1025 + c] = p;
                sum += p;
            }
            #pragma unroll
            for (int off = 16; off; off >>= 1) sum += __shfl_xor_sync(0xffffffffu, sum, off);
            if (lane == 0) rowinv[r] = 1.f / sum;
        }
    }
    __syncthreads();

    // 16x16 sum-pool: pooled[kb] = sum_{r,j} P[r][kb*16+j]
    {
        int kb = t >> 2, part = t & 3;
        float acc = 0.f;
        #pragma unroll
        for (int i = 0; i < 4; i++) {
            int r = (part << 2) + i;
            float s = 0.f;
            #pragma unroll
            for (int j = 0; j < 16; j++) s += S[r * 1025 + (kb << 4) + j];
            acc += s * rowinv[r];
        }
        ppart[t] = acc;
    }
    __syncthreads();
    if (t < 64)
        pooled[t] = ppart[t * 4] + ppart[t * 4 + 1] + ppart[t * 4 + 2] + ppart[t * 4 + 3];
    __syncthreads();
    if (t == 0) { float tot = 0.f; for (int i = 0; i < 64; i++) tot += pooled[i]; total_s = tot; }
    __syncthreads();

    // keep iff cumulative pooled mass of strictly-higher-ranked blocks < 50%.
    // Rank: descending value, ties broken by ascending index (stable argsort of -pooling).
    if (t < 64) {
        float mine = pooled[t], before = 0.f;
        for (int j = 0; j < 64; j++) {
            float pj = pooled[j];
            if (pj > mine || (pj == mine && j < t)) before += pj;
        }
        keepflag[t] = (before < 0.5f * total_s) ? 1 : 0;
    }
    __syncthreads();
    if (t == 0) {
        int cnt = 0;
        for (int b = 0; b < 64; b++)
            if (keepflag[b]) g_keep_list[h][qb][cnt++] = b;
        g_keep_count[h][qb] = cnt;
    }
}

// ---------------------------------------------------------------------------
// Kernel 2: block-sparse flash attention over kept blocks.
// Grid (64 qblocks, 8 heads), 128 threads.
// Thread tiles: S phase 8 rows x 4 strided cols; PV phase 8 rows x 4 strided dims.
// Dynamic smem: Q,K,V,P each 64x65 (66560 B).
// ---------------------------------------------------------------------------
__global__ __launch_bounds__(128, 3) void attn_kernel(
    const float* __restrict__ q, const float* __restrict__ k,
    const float* __restrict__ v, float* __restrict__ out)
{
    const int qb = blockIdx.x, h = blockIdx.y;
    const int t = threadIdx.x;
    extern __shared__ float dyna[];
    float* Qs = dyna;            // 64 x 65
    float* Ks = Qs + 64 * 65;
    float* Vs = Ks + 64 * 65;
    float* Ps = Vs + 64 * 65;
    __shared__ float m_s[64], l_s[64];
    __shared__ int keep_s[64];
    __shared__ int cnt_s;

    if (t == 0) cnt_s = g_keep_count[h][qb];
    if (t < 64) {
        keep_s[t] = g_keep_list[h][qb][t];
        m_s[t] = -1e30f;
        l_s[t] = 0.f;
    }
    for (int i = t; i < 1024; i += 128) {
        int r = i >> 4, c4 = (i & 15) << 2;
        float4 val = *reinterpret_cast<const float4*>(q + ((((h << 12) + (qb << 6) + r) << 6) + c4));
        Qs[r * 65 + c4 + 0] = val.x * 0.125f; Qs[r * 65 + c4 + 1] = val.y * 0.125f;
        Qs[r * 65 + c4 + 2] = val.z * 0.125f; Qs[r * 65 + c4 + 3] = val.w * 0.125f;
    }
    __syncthreads();

    const int tr = t >> 4;   // 0..7  -> rows tr*8 .. tr*8+7
    const int tc = t & 15;   // 0..15 -> cols/dims {tc, tc+16, tc+32, tc+48}
    float acc[8][4] = {};
    const int cnt = cnt_s;

    for (int it = 0; it < cnt; it++) {
        const int kb = keep_s[it];
        const int base = (((h << 12) + (kb << 6)) << 6);
        for (int i = t; i < 1024; i += 128) {
            int r = i >> 4, c4 = (i & 15) << 2;
            float4 kv4 = *reinterpret_cast<const float4*>(k + base + (r << 6) + c4);
            float4 vv4 = *reinterpret_cast<const float4*>(v + base + (r << 6) + c4);
            Ks[r * 65 + c4 + 0] = kv4.x; Ks[r * 65 + c4 + 1] = kv4.y;
            Ks[r * 65 + c4 + 2] = kv4.z; Ks[r * 65 + c4 + 3] = kv4.w;
            Vs[r * 65 + c4 + 0] = vv4.x; Vs[r * 65 + c4 + 1] = vv4.y;
            Vs[r * 65 + c4 + 2] = vv4.z; Vs[r * 65 + c4 + 3] = vv4.w;
        }
        __syncthreads();

        // S = Q K^T for this 64x64 block (already scaled by 1/8 via Q).
        float sacc[8][4] = {};
        #pragma unroll 8
        for (int d = 0; d < 64; d++) {
            float qv[8], kv[4];
            #pragma unroll
            for (int i = 0; i < 8; i++) qv[i] = Qs[((tr << 3) + i) * 65 + d];
            #pragma unroll
            for (int j = 0; j < 4; j++) kv[j] = Ks[(tc + (j << 4)) * 65 + d];
            #pragma unroll
            for (int i = 0; i < 8; i++)
                #pragma unroll
                for (int j = 0; j < 4; j++) sacc[i][j] += qv[i] * kv[j];
        }

        // Online softmax per row; row r owned by the 16 lanes sharing tr (same warp half).
        #pragma unroll
        for (int i = 0; i < 8; i++) {
            const int r = (tr << 3) + i;
            float mx = fmaxf(fmaxf(sacc[i][0], sacc[i][1]), fmaxf(sacc[i][2], sacc[i][3]));
            #pragma unroll
            for (int off = 8; off; off >>= 1) mx = fmaxf(mx, __shfl_xor_sync(0xffffffffu, mx, off, 16));
            const float mold = m_s[r];
            const float mnew = fmaxf(mold, mx);
            float p0 = __expf(sacc[i][0] - mnew);
            float p1 = __expf(sacc[i][1] - mnew);
            float p2 = __expf(sacc[i][2] - mnew);
            float p3 = __expf(sacc[i][3] - mnew);
            float rs = p0 + p1 + p2 + p3;
            #pragma unroll
            for (int off = 8; off; off >>= 1) rs += __shfl_xor_sync(0xffffffffu, rs, off, 16);
            Ps[r * 65 + tc +  0] = p0;
            Ps[r * 65 + tc + 16] = p1;
            Ps[r * 65 + tc + 32] = p2;
            Ps[r * 65 + tc + 48] = p3;
            const float alpha = __expf(mold - mnew);
            if (tc == 0) { m_s[r] = mnew; l_s[r] = l_s[r] * alpha + rs; }
            #pragma unroll
            for (int j = 0; j < 4; j++) acc[i][j] *= alpha;
        }
        __syncthreads();

        // acc += P @ V
        #pragma unroll 4
        for (int j = 0; j < 64; j++) {
            float pv[8], vv[4];
            #pragma unroll
            for (int i = 0; i < 8; i++) pv[i] = Ps[((tr << 3) + i) * 65 + j];
            #pragma unroll
            for (int jj = 0; jj < 4; jj++) vv[jj] = Vs[j * 65 + tc + (jj << 4)];
            #pragma unroll
            for (int i = 0; i < 8; i++)
                #pragma unroll
                for (int jj = 0; jj < 4; jj++) acc[i][jj] += pv[i] * vv[jj];
        }
        __syncthreads();
    }

    #pragma unroll
    for (int i = 0; i < 8; i++) {
        const int r = (tr << 3) + i;
        const float inv = 1.f / l_s[r];
        const int gbase = (((h << 12) + (qb << 6) + r) << 6);
        #pragma unroll
        for (int j = 0; j < 4; j++) out[gbase + tc + (j << 4)] = acc[i][j] * inv;
    }
}

extern "C" void kernel_launch(void* const* d_in, const int* in_sizes, int n_in,
                              void* d_out, int out_size) {
    const float* q  = (const float*)d_in[0];
    const float* k  = (const float*)d_in[1];
    const float* v  = (const float*)d_in[2];
    const int* siq  = (const int*)d_in[3];
    const int* sik  = (const int*)d_in[4];
    float* out = (float*)d_out;

    const int pool_smem = (256 * 65 + 16 * 1025) * (int)sizeof(float);  // 132160
    const int attn_smem = 4 * 64 * 65 * (int)sizeof(float);             // 66560
    cudaFuncSetAttribute(pool_mask_kernel, cudaFuncAttributeMaxDynamicSharedMemorySize, pool_smem);
    cudaFuncSetAttribute(attn_kernel, cudaFuncAttributeMaxDynamicSharedMemorySize, attn_smem);

    dim3 grid(64, 8);
    pool_mask_kernel<<<grid, 256, pool_smem>>>(q, k, siq, sik);
    attn_kernel<<<grid, 128, attn_smem>>>(q, k, v, out);
}